// round 1
// baseline (speedup 1.0000x reference)
#include <cuda_runtime.h>
#include <cuda_bf16.h>
#include <math.h>
#include <stdint.h>

// Problem constants
#define BB    64      // batch
#define SS    512     // seq len
#define EMBD  512
#define HID   1024
#define NOUT  2

// Persistent recurrent kernel config
#define NB    128     // persistent blocks (<= 148 SMs, 1 block/SM)
#define TPB   256
#define JW    8       // HID / NB columns per block

// ---------------------------------------------------------------------------
// Device globals (scratch; allocation-free rule)
// ---------------------------------------------------------------------------
__device__ float g_xe0[(size_t)SS * HID * BB];  // [t][j][b]  precomputed x@W_ih0+b_hh0
__device__ float g_h0[2][HID * BB];             // [k][b] transposed h state, ping-pong
__device__ float g_h1[2][HID * BB];
__device__ unsigned g_bar;                      // zero-init; self-resetting
__device__ unsigned g_gen;

// ---------------------------------------------------------------------------
// Software grid barrier (all NB blocks resident in one wave)
// ---------------------------------------------------------------------------
__device__ __forceinline__ void grid_sync() {
    __threadfence();          // every thread: publish prior global stores
    __syncthreads();
    if (threadIdx.x == 0) {
        volatile unsigned* genp = &g_gen;
        unsigned my = *genp;
        if (atomicAdd(&g_bar, 1u) == NB - 1) {
            atomicExch(&g_bar, 0u);
            __threadfence();
            atomicAdd(&g_gen, 1u);
        } else {
            while (*genp == my) { }
        }
    }
    __syncthreads();
}

// ---------------------------------------------------------------------------
// Kernel 1: xe0[t][j][b] = sum_e emb[x[b][t]][e] * W_ih0[e][j] + b_hh0[j]
// Tiled fp32 GEMM, one block = (one t) x (64 columns)
// ---------------------------------------------------------------------------
__global__ void __launch_bounds__(256)
emb_gemm_kernel(const int* __restrict__ x, const float* __restrict__ emb,
                const float* __restrict__ Wih0, const float* __restrict__ bhh0) {
    __shared__ float As[64][17];   // [row=b][kk]  (+pad to kill bank conflicts)
    __shared__ float Bs[16][64];   // [kk][col]
    __shared__ int   ids[64];

    const int t   = blockIdx.x;
    const int j0  = blockIdx.y * 64;
    const int tid = threadIdx.x;

    if (tid < 64) ids[tid] = x[tid * SS + t];   // x is [B][S]
    __syncthreads();

    const int ty = tid >> 4;   // 0..15 -> rows ty*4..ty*4+3
    const int tx = tid & 15;   // 0..15 -> cols tx*4..tx*4+3
    float acc[4][4];
    #pragma unroll
    for (int i = 0; i < 4; i++)
        #pragma unroll
        for (int j = 0; j < 4; j++) acc[i][j] = 0.f;

    for (int k0 = 0; k0 < EMBD; k0 += 16) {
        #pragma unroll
        for (int p = 0; p < 4; p++) {
            int r  = (tid >> 4) + p * 16;
            int kk = tid & 15;
            As[r][kk] = emb[(size_t)ids[r] * EMBD + k0 + kk];
        }
        #pragma unroll
        for (int p = 0; p < 4; p++) {
            int kk = (tid >> 6) + p * 4;
            int c  = tid & 63;
            Bs[kk][c] = Wih0[(size_t)(k0 + kk) * HID + j0 + c];
        }
        __syncthreads();
        #pragma unroll
        for (int kk = 0; kk < 16; kk++) {
            float a0 = As[ty * 4 + 0][kk];
            float a1 = As[ty * 4 + 1][kk];
            float a2 = As[ty * 4 + 2][kk];
            float a3 = As[ty * 4 + 3][kk];
            float4 bv = *reinterpret_cast<const float4*>(&Bs[kk][tx * 4]);
            float bw[4] = {bv.x, bv.y, bv.z, bv.w};
            #pragma unroll
            for (int j = 0; j < 4; j++) {
                acc[0][j] = fmaf(a0, bw[j], acc[0][j]);
                acc[1][j] = fmaf(a1, bw[j], acc[1][j]);
                acc[2][j] = fmaf(a2, bw[j], acc[2][j]);
                acc[3][j] = fmaf(a3, bw[j], acc[3][j]);
            }
        }
        __syncthreads();
    }

    // epilogue: transposed store  xe0[t][col][b]  (+bias)
    #pragma unroll
    for (int j = 0; j < 4; j++) {
        int col = j0 + tx * 4 + j;
        float bias = bhh0[col];
        float4 v;
        v.x = acc[0][j] + bias;
        v.y = acc[1][j] + bias;
        v.z = acc[2][j] + bias;
        v.w = acc[3][j] + bias;
        *reinterpret_cast<float4*>(&g_xe0[((size_t)t * HID + col) * BB + ty * 4]) = v;
    }
}

// ---------------------------------------------------------------------------
// Kernel 2: persistent recurrent kernel.
// Block bid owns columns jg = bid*8 .. +7 of all three recurrent matrices,
// held in SMEM for the whole sequence. h state is [k][b] in global, ping-pong.
// Thread (bq = tid&15, kc = tid>>4): batch quad bq*4..+3, K-chunk kc*64..+63.
// ---------------------------------------------------------------------------
#define SMEM_FLOATS (3 * HID * JW + TPB * 32)
#define SMEM_BYTES  (SMEM_FLOATS * 4)

__global__ void __launch_bounds__(TPB, 1)
rnn_kernel(const float* __restrict__ Whh0, const float* __restrict__ Wih1,
           const float* __restrict__ Whh1, const float* __restrict__ bhh1) {
    extern __shared__ float smem[];
    float* ws0  = smem;                    // [k][jj]  W_hh0 slice
    float* ws1i = smem + HID * JW;         // W_ih1 slice
    float* ws1h = smem + 2 * HID * JW;     // W_hh1 slice
    float* red  = smem + 3 * HID * JW;     // [tid][32] reduction scratch

    const int tid = threadIdx.x;
    const int bid = blockIdx.x;
    const int jg  = bid * JW;

    // Load weight column-slices into SMEM (stays resident for all 512 steps)
    for (int i = tid; i < HID * JW; i += TPB) {
        int k = i >> 3, jj = i & 7;
        ws0[i]  = Whh0[(size_t)k * HID + jg + jj];
        ws1i[i] = Wih1[(size_t)k * HID + jg + jj];
        ws1h[i] = Whh1[(size_t)k * HID + jg + jj];
    }
    // Zero initial h state (parity 0)
    for (int i = bid * TPB + tid; i < HID * BB; i += NB * TPB) {
        g_h0[0][i] = 0.f;
        g_h1[0][i] = 0.f;
    }
    grid_sync();

    const int bq = tid & 15;   // batch quad
    const int kc = tid >> 4;   // K-chunk
    const int k0 = kc * 64;

    for (int t = 0; t < SS; t++) {
        const int p = t & 1;
        const int q = p ^ 1;

        // ================= phase A: h0_new = tanh(xe0[t] + h0 @ W_hh0) ======
        {
            const float* h0r = g_h0[p];
            float*       h0w = g_h0[q];
            float acc[4][8];
            #pragma unroll
            for (int i = 0; i < 4; i++)
                #pragma unroll
                for (int j = 0; j < 8; j++) acc[i][j] = 0.f;

            #pragma unroll 4
            for (int k = k0; k < k0 + 64; k++) {
                float4 hv = __ldcg(reinterpret_cast<const float4*>(h0r + k * BB + bq * 4));
                float4 w0 = *reinterpret_cast<const float4*>(ws0 + k * 8);
                float4 w1 = *reinterpret_cast<const float4*>(ws0 + k * 8 + 4);
                float hb[4] = {hv.x, hv.y, hv.z, hv.w};
                float wv[8] = {w0.x, w0.y, w0.z, w0.w, w1.x, w1.y, w1.z, w1.w};
                #pragma unroll
                for (int b = 0; b < 4; b++)
                    #pragma unroll
                    for (int j = 0; j < 8; j++)
                        acc[b][j] = fmaf(hb[b], wv[j], acc[b][j]);
            }
            #pragma unroll
            for (int b = 0; b < 4; b++)
                #pragma unroll
                for (int j = 0; j < 8; j++)
                    red[tid * 32 + b * 8 + j] = acc[b][j];
            __syncthreads();
            #pragma unroll
            for (int o = tid; o < BB * JW; o += TPB) {   // 2 outputs/thread
                int b = o & 63, jj = o >> 6;
                int bq2 = b >> 2, bb2 = b & 3;
                float s = 0.f;
                #pragma unroll
                for (int kk = 0; kk < 16; kk++)
                    s += red[((kk << 4) + bq2) * 32 + bb2 * 8 + jj];
                s += g_xe0[((size_t)t * HID + jg + jj) * BB + b];
                __stcg(h0w + (jg + jj) * BB + b, tanhf(s));
            }
        }
        grid_sync();

        // ======= phase B: h1_new = tanh(h0_new@W_ih1 + h1@W_hh1 + b_hh1) ====
        {
            const float* h0n = g_h0[q];
            const float* h1r = g_h1[p];
            float*       h1w = g_h1[q];
            float acc[4][8];
            #pragma unroll
            for (int i = 0; i < 4; i++)
                #pragma unroll
                for (int j = 0; j < 8; j++) acc[i][j] = 0.f;

            #pragma unroll 2
            for (int k = k0; k < k0 + 64; k++) {
                float4 av = __ldcg(reinterpret_cast<const float4*>(h0n + k * BB + bq * 4));
                float4 cv = __ldcg(reinterpret_cast<const float4*>(h1r + k * BB + bq * 4));
                float4 wi0 = *reinterpret_cast<const float4*>(ws1i + k * 8);
                float4 wi1 = *reinterpret_cast<const float4*>(ws1i + k * 8 + 4);
                float4 wh0 = *reinterpret_cast<const float4*>(ws1h + k * 8);
                float4 wh1 = *reinterpret_cast<const float4*>(ws1h + k * 8 + 4);
                float ab[4] = {av.x, av.y, av.z, av.w};
                float cb[4] = {cv.x, cv.y, cv.z, cv.w};
                float wi[8] = {wi0.x, wi0.y, wi0.z, wi0.w, wi1.x, wi1.y, wi1.z, wi1.w};
                float wh[8] = {wh0.x, wh0.y, wh0.z, wh0.w, wh1.x, wh1.y, wh1.z, wh1.w};
                #pragma unroll
                for (int b = 0; b < 4; b++)
                    #pragma unroll
                    for (int j = 0; j < 8; j++) {
                        acc[b][j] = fmaf(ab[b], wi[j], acc[b][j]);
                        acc[b][j] = fmaf(cb[b], wh[j], acc[b][j]);
                    }
            }
            #pragma unroll
            for (int b = 0; b < 4; b++)
                #pragma unroll
                for (int j = 0; j < 8; j++)
                    red[tid * 32 + b * 8 + j] = acc[b][j];
            __syncthreads();
            #pragma unroll
            for (int o = tid; o < BB * JW; o += TPB) {
                int b = o & 63, jj = o >> 6;
                int bq2 = b >> 2, bb2 = b & 3;
                float s = 0.f;
                #pragma unroll
                for (int kk = 0; kk < 16; kk++)
                    s += red[((kk << 4) + bq2) * 32 + bb2 * 8 + jj];
                s += bhh1[jg + jj];
                __stcg(h1w + (jg + jj) * BB + b, tanhf(s));
            }
        }
        grid_sync();
    }
}

// ---------------------------------------------------------------------------
// Kernel 3: out[b][o] = h1_final[.][b] . W_out[.][o] + b_out[o]
// Final h1 parity: last write at t=511 goes to buffer (511+1)&1 = 0.
// ---------------------------------------------------------------------------
__global__ void __launch_bounds__(128)
out_kernel(const float* __restrict__ Wout, const float* __restrict__ bout,
           float* __restrict__ out) {
    const int tid = threadIdx.x;   // 128 threads = 64 b x 2 o
    const int b = tid & 63;
    const int o = tid >> 6;
    const float* h = g_h1[0];
    float s0 = 0.f, s1 = 0.f, s2 = 0.f, s3 = 0.f;
    #pragma unroll 4
    for (int k = 0; k < HID; k += 4) {
        s0 = fmaf(h[(k + 0) * BB + b], Wout[(size_t)(k + 0) * NOUT + o], s0);
        s1 = fmaf(h[(k + 1) * BB + b], Wout[(size_t)(k + 1) * NOUT + o], s1);
        s2 = fmaf(h[(k + 2) * BB + b], Wout[(size_t)(k + 2) * NOUT + o], s2);
        s3 = fmaf(h[(k + 3) * BB + b], Wout[(size_t)(k + 3) * NOUT + o], s3);
    }
    out[b * NOUT + o] = s0 + s1 + s2 + s3 + bout[o];
}

// ---------------------------------------------------------------------------
extern "C" void kernel_launch(void* const* d_in, const int* in_sizes, int n_in,
                              void* d_out, int out_size) {
    const int*   x    = (const int*)  d_in[0];
    const float* emb  = (const float*)d_in[1];
    const float* Wih0 = (const float*)d_in[2];
    const float* Whh0 = (const float*)d_in[3];
    const float* bhh0 = (const float*)d_in[4];
    const float* Wih1 = (const float*)d_in[5];
    const float* Whh1 = (const float*)d_in[6];
    const float* bhh1 = (const float*)d_in[7];
    const float* Wout = (const float*)d_in[8];
    const float* bout = (const float*)d_in[9];
    float* out = (float*)d_out;

    cudaFuncSetAttribute(rnn_kernel, cudaFuncAttributeMaxDynamicSharedMemorySize,
                         SMEM_BYTES);

    emb_gemm_kernel<<<dim3(SS, HID / 64), 256>>>(x, emb, Wih0, bhh0);
    rnn_kernel<<<NB, TPB, SMEM_BYTES>>>(Whh0, Wih1, Whh1, bhh1);
    out_kernel<<<1, 128>>>(Wout, bout, out);
}

// round 2
// speedup vs baseline: 1.3177x; 1.3177x over previous
#include <cuda_runtime.h>
#include <cuda_bf16.h>
#include <math.h>
#include <stdint.h>

// Problem constants
#define BB    64      // batch
#define SS    512     // seq len
#define EMBD  512
#define HID   1024
#define NOUT  2

// Persistent recurrent kernel config
#define NB    128     // persistent blocks (1 block/SM, single wave)
#define TPB   256
#define JW    8       // HID / NB columns per block

// ---------------------------------------------------------------------------
// Device globals (scratch; allocation-free rule)
// ---------------------------------------------------------------------------
__device__ float g_xe0[(size_t)SS * HID * BB];  // [t][j][b]  precomputed x@W_ih0+b_hh0
__device__ float g_h0[2][HID * BB];             // [k][b] transposed h state, ping-pong
__device__ float g_h1[2][HID * BB];
__device__ unsigned g_bar;                      // zero-init; self-resetting
__device__ unsigned g_gen;

// ---------------------------------------------------------------------------
// Packed fp32x2 FMA (sm_100a): d = a*b + d elementwise on a float pair.
// ptxas never emits FFMA2 from C++; must come from PTX.
// ---------------------------------------------------------------------------
__device__ __forceinline__ void ffma2(unsigned long long& d,
                                      unsigned long long a,
                                      unsigned long long b) {
    asm("fma.rn.f32x2 %0, %1, %2, %0;" : "+l"(d) : "l"(a), "l"(b));
}
__device__ __forceinline__ unsigned long long bcast2(float v) {
    unsigned long long r;
    asm("mov.b64 %0, {%1, %1};" : "=l"(r) : "f"(v));
    return r;
}

// ---------------------------------------------------------------------------
// Software grid barrier (all NB blocks resident in one wave)
// ---------------------------------------------------------------------------
__device__ __forceinline__ void grid_sync() {
    __threadfence();
    __syncthreads();
    if (threadIdx.x == 0) {
        volatile unsigned* genp = &g_gen;
        unsigned my = *genp;
        if (atomicAdd(&g_bar, 1u) == NB - 1) {
            atomicExch(&g_bar, 0u);
            __threadfence();
            atomicAdd(&g_gen, 1u);
        } else {
            while (*genp == my) { }
        }
    }
    __syncthreads();
}

// ---------------------------------------------------------------------------
// Kernel 1: xe0[t][j][b] = sum_e emb[x[b][t]][e] * W_ih0[e][j] + b_hh0[j]
// ---------------------------------------------------------------------------
__global__ void __launch_bounds__(256)
emb_gemm_kernel(const int* __restrict__ x, const float* __restrict__ emb,
                const float* __restrict__ Wih0, const float* __restrict__ bhh0) {
    __shared__ float As[64][17];
    __shared__ float Bs[16][64];
    __shared__ int   ids[64];

    const int t   = blockIdx.x;
    const int j0  = blockIdx.y * 64;
    const int tid = threadIdx.x;

    if (tid < 64) ids[tid] = x[tid * SS + t];
    __syncthreads();

    const int ty = tid >> 4;
    const int tx = tid & 15;
    float acc[4][4];
    #pragma unroll
    for (int i = 0; i < 4; i++)
        #pragma unroll
        for (int j = 0; j < 4; j++) acc[i][j] = 0.f;

    for (int k0 = 0; k0 < EMBD; k0 += 16) {
        #pragma unroll
        for (int p = 0; p < 4; p++) {
            int r  = (tid >> 4) + p * 16;
            int kk = tid & 15;
            As[r][kk] = emb[(size_t)ids[r] * EMBD + k0 + kk];
        }
        #pragma unroll
        for (int p = 0; p < 4; p++) {
            int kk = (tid >> 6) + p * 4;
            int c  = tid & 63;
            Bs[kk][c] = Wih0[(size_t)(k0 + kk) * HID + j0 + c];
        }
        __syncthreads();
        #pragma unroll
        for (int kk = 0; kk < 16; kk++) {
            float a0 = As[ty * 4 + 0][kk];
            float a1 = As[ty * 4 + 1][kk];
            float a2 = As[ty * 4 + 2][kk];
            float a3 = As[ty * 4 + 3][kk];
            float4 bv = *reinterpret_cast<const float4*>(&Bs[kk][tx * 4]);
            float bw[4] = {bv.x, bv.y, bv.z, bv.w};
            #pragma unroll
            for (int j = 0; j < 4; j++) {
                acc[0][j] = fmaf(a0, bw[j], acc[0][j]);
                acc[1][j] = fmaf(a1, bw[j], acc[1][j]);
                acc[2][j] = fmaf(a2, bw[j], acc[2][j]);
                acc[3][j] = fmaf(a3, bw[j], acc[3][j]);
            }
        }
        __syncthreads();
    }

    #pragma unroll
    for (int j = 0; j < 4; j++) {
        int col = j0 + tx * 4 + j;
        float bias = bhh0[col];
        float4 v;
        v.x = acc[0][j] + bias;
        v.y = acc[1][j] + bias;
        v.z = acc[2][j] + bias;
        v.w = acc[3][j] + bias;
        *reinterpret_cast<float4*>(&g_xe0[((size_t)t * HID + col) * BB + ty * 4]) = v;
    }
}

// ---------------------------------------------------------------------------
// Kernel 2: persistent recurrent kernel with packed f32x2 FMAs.
// Block bid owns columns jg = bid*8 .. +7 of the three recurrent matrices,
// resident in SMEM. h state is [k][b] in global, ping-pong, via .cg.
// Thread (bq = tid&15, kc = tid>>4): batch quad bq*4..+3, K-chunk kc*64..+63.
// Accumulators pack column pairs: acc[b][jp] = (col 2jp, col 2jp+1).
// ---------------------------------------------------------------------------
#define SMEM_FLOATS (3 * HID * JW + TPB * 32)
#define SMEM_BYTES  (SMEM_FLOATS * 4)

__global__ void __launch_bounds__(TPB, 1)
rnn_kernel(const float* __restrict__ Whh0, const float* __restrict__ Wih1,
           const float* __restrict__ Whh1, const float* __restrict__ bhh1) {
    extern __shared__ float smem[];
    float* ws0  = smem;                    // W_hh0 slice [k][8]
    float* ws1i = smem + HID * JW;         // W_ih1 slice
    float* ws1h = smem + 2 * HID * JW;     // W_hh1 slice
    float* red  = smem + 3 * HID * JW;     // [tid][32] reduction scratch

    const int tid = threadIdx.x;
    const int bid = blockIdx.x;
    const int jg  = bid * JW;

    for (int i = tid; i < HID * JW; i += TPB) {
        int k = i >> 3, jj = i & 7;
        ws0[i]  = Whh0[(size_t)k * HID + jg + jj];
        ws1i[i] = Wih1[(size_t)k * HID + jg + jj];
        ws1h[i] = Whh1[(size_t)k * HID + jg + jj];
    }
    for (int i = bid * TPB + tid; i < HID * BB; i += NB * TPB) {
        g_h0[0][i] = 0.f;
        g_h1[0][i] = 0.f;
    }
    grid_sync();

    const int bq = tid & 15;
    const int kc = tid >> 4;
    const int k0 = kc * 64;

    for (int t = 0; t < SS; t++) {
        const int p = t & 1;
        const int q = p ^ 1;

        // ================= phase A: h0_new = tanh(xe0[t] + h0 @ W_hh0) ======
        {
            const float* h0r = g_h0[p];
            float*       h0w = g_h0[q];
            unsigned long long acc[4][4];
            #pragma unroll
            for (int b = 0; b < 4; b++)
                #pragma unroll
                for (int jp = 0; jp < 4; jp++) acc[b][jp] = 0ull;

            #pragma unroll 4
            for (int k = k0; k < k0 + 64; k++) {
                float4 hv = __ldcg(reinterpret_cast<const float4*>(h0r + k * BB + bq * 4));
                const unsigned long long* wp =
                    reinterpret_cast<const unsigned long long*>(ws0 + k * 8);
                unsigned long long w0 = wp[0], w1 = wp[1], w2 = wp[2], w3 = wp[3];
                unsigned long long hp0 = bcast2(hv.x), hp1 = bcast2(hv.y);
                unsigned long long hp2 = bcast2(hv.z), hp3 = bcast2(hv.w);
                ffma2(acc[0][0], hp0, w0); ffma2(acc[0][1], hp0, w1);
                ffma2(acc[0][2], hp0, w2); ffma2(acc[0][3], hp0, w3);
                ffma2(acc[1][0], hp1, w0); ffma2(acc[1][1], hp1, w1);
                ffma2(acc[1][2], hp1, w2); ffma2(acc[1][3], hp1, w3);
                ffma2(acc[2][0], hp2, w0); ffma2(acc[2][1], hp2, w1);
                ffma2(acc[2][2], hp2, w2); ffma2(acc[2][3], hp2, w3);
                ffma2(acc[3][0], hp3, w0); ffma2(acc[3][1], hp3, w1);
                ffma2(acc[3][2], hp3, w2); ffma2(acc[3][3], hp3, w3);
            }
            #pragma unroll
            for (int b = 0; b < 4; b++)
                #pragma unroll
                for (int jp = 0; jp < 4; jp++)
                    *reinterpret_cast<unsigned long long*>(
                        red + tid * 32 + b * 8 + jp * 2) = acc[b][jp];
            __syncthreads();
            #pragma unroll
            for (int o = tid; o < BB * JW; o += TPB) {   // 2 outputs/thread
                int b = o & 63, jj = o >> 6;
                int bq2 = b >> 2, bb2 = b & 3;
                float s = 0.f;
                #pragma unroll
                for (int kk = 0; kk < 16; kk++)
                    s += red[((kk << 4) + bq2) * 32 + bb2 * 8 + jj];
                s += g_xe0[((size_t)t * HID + jg + jj) * BB + b];
                __stcg(h0w + (jg + jj) * BB + b, tanhf(s));
            }
        }
        grid_sync();

        // ======= phase B: h1_new = tanh(h0_new@W_ih1 + h1@W_hh1 + b_hh1) ====
        {
            const float* h0n = g_h0[q];
            const float* h1r = g_h1[p];
            float*       h1w = g_h1[q];
            unsigned long long acc[4][4];
            #pragma unroll
            for (int b = 0; b < 4; b++)
                #pragma unroll
                for (int jp = 0; jp < 4; jp++) acc[b][jp] = 0ull;

            #pragma unroll 4
            for (int k = k0; k < k0 + 64; k++) {
                float4 av = __ldcg(reinterpret_cast<const float4*>(h0n + k * BB + bq * 4));
                float4 cv = __ldcg(reinterpret_cast<const float4*>(h1r + k * BB + bq * 4));
                const unsigned long long* wip =
                    reinterpret_cast<const unsigned long long*>(ws1i + k * 8);
                const unsigned long long* whp =
                    reinterpret_cast<const unsigned long long*>(ws1h + k * 8);
                unsigned long long wi0 = wip[0], wi1 = wip[1], wi2 = wip[2], wi3 = wip[3];
                unsigned long long wh0 = whp[0], wh1 = whp[1], wh2 = whp[2], wh3 = whp[3];
                unsigned long long ap0 = bcast2(av.x), ap1 = bcast2(av.y);
                unsigned long long ap2 = bcast2(av.z), ap3 = bcast2(av.w);
                unsigned long long cp0 = bcast2(cv.x), cp1 = bcast2(cv.y);
                unsigned long long cp2 = bcast2(cv.z), cp3 = bcast2(cv.w);
                ffma2(acc[0][0], ap0, wi0); ffma2(acc[0][1], ap0, wi1);
                ffma2(acc[0][2], ap0, wi2); ffma2(acc[0][3], ap0, wi3);
                ffma2(acc[1][0], ap1, wi0); ffma2(acc[1][1], ap1, wi1);
                ffma2(acc[1][2], ap1, wi2); ffma2(acc[1][3], ap1, wi3);
                ffma2(acc[2][0], ap2, wi0); ffma2(acc[2][1], ap2, wi1);
                ffma2(acc[2][2], ap2, wi2); ffma2(acc[2][3], ap2, wi3);
                ffma2(acc[3][0], ap3, wi0); ffma2(acc[3][1], ap3, wi1);
                ffma2(acc[3][2], ap3, wi2); ffma2(acc[3][3], ap3, wi3);
                ffma2(acc[0][0], cp0, wh0); ffma2(acc[0][1], cp0, wh1);
                ffma2(acc[0][2], cp0, wh2); ffma2(acc[0][3], cp0, wh3);
                ffma2(acc[1][0], cp1, wh0); ffma2(acc[1][1], cp1, wh1);
                ffma2(acc[1][2], cp1, wh2); ffma2(acc[1][3], cp1, wh3);
                ffma2(acc[2][0], cp2, wh0); ffma2(acc[2][1], cp2, wh1);
                ffma2(acc[2][2], cp2, wh2); ffma2(acc[2][3], cp2, wh3);
                ffma2(acc[3][0], cp3, wh0); ffma2(acc[3][1], cp3, wh1);
                ffma2(acc[3][2], cp3, wh2); ffma2(acc[3][3], cp3, wh3);
            }
            #pragma unroll
            for (int b = 0; b < 4; b++)
                #pragma unroll
                for (int jp = 0; jp < 4; jp++)
                    *reinterpret_cast<unsigned long long*>(
                        red + tid * 32 + b * 8 + jp * 2) = acc[b][jp];
            __syncthreads();
            #pragma unroll
            for (int o = tid; o < BB * JW; o += TPB) {
                int b = o & 63, jj = o >> 6;
                int bq2 = b >> 2, bb2 = b & 3;
                float s = 0.f;
                #pragma unroll
                for (int kk = 0; kk < 16; kk++)
                    s += red[((kk << 4) + bq2) * 32 + bb2 * 8 + jj];
                s += bhh1[jg + jj];
                __stcg(h1w + (jg + jj) * BB + b, tanhf(s));
            }
        }
        grid_sync();
    }
}

// ---------------------------------------------------------------------------
// Kernel 3: out[b][o] = h1_final[.][b] . W_out[.][o] + b_out[o]
// Final h1 parity: last write at t=511 goes to buffer (511+1)&1 = 0.
// ---------------------------------------------------------------------------
__global__ void __launch_bounds__(128)
out_kernel(const float* __restrict__ Wout, const float* __restrict__ bout,
           float* __restrict__ out) {
    const int tid = threadIdx.x;
    const int b = tid & 63;
    const int o = tid >> 6;
    const float* h = g_h1[0];
    float s0 = 0.f, s1 = 0.f, s2 = 0.f, s3 = 0.f;
    #pragma unroll 4
    for (int k = 0; k < HID; k += 4) {
        s0 = fmaf(h[(k + 0) * BB + b], Wout[(size_t)(k + 0) * NOUT + o], s0);
        s1 = fmaf(h[(k + 1) * BB + b], Wout[(size_t)(k + 1) * NOUT + o], s1);
        s2 = fmaf(h[(k + 2) * BB + b], Wout[(size_t)(k + 2) * NOUT + o], s2);
        s3 = fmaf(h[(k + 3) * BB + b], Wout[(size_t)(k + 3) * NOUT + o], s3);
    }
    out[b * NOUT + o] = s0 + s1 + s2 + s3 + bout[o];
}

// ---------------------------------------------------------------------------
extern "C" void kernel_launch(void* const* d_in, const int* in_sizes, int n_in,
                              void* d_out, int out_size) {
    const int*   x    = (const int*)  d_in[0];
    const float* emb  = (const float*)d_in[1];
    const float* Wih0 = (const float*)d_in[2];
    const float* Whh0 = (const float*)d_in[3];
    const float* bhh0 = (const float*)d_in[4];
    const float* Wih1 = (const float*)d_in[5];
    const float* Whh1 = (const float*)d_in[6];
    const float* bhh1 = (const float*)d_in[7];
    const float* Wout = (const float*)d_in[8];
    const float* bout = (const float*)d_in[9];
    float* out = (float*)d_out;

    cudaFuncSetAttribute(rnn_kernel, cudaFuncAttributeMaxDynamicSharedMemorySize,
                         SMEM_BYTES);

    emb_gemm_kernel<<<dim3(SS, HID / 64), 256>>>(x, emb, Wih0, bhh0);
    rnn_kernel<<<NB, TPB, SMEM_BYTES>>>(Whh0, Wih1, Whh1, bhh1);
    out_kernel<<<1, 128>>>(Wout, bout, out);
}